// round 3
// baseline (speedup 1.0000x reference)
#include <cuda_runtime.h>
#include <cuda_bf16.h>
#include <cstdint>

// Batched inverse of 3x3 upper-triangular matrices, rows of 9 fp32.
//   in : [a b c | . d e | . . f]
//   out: [1/a  -b/(ad)  (be-cd)/(adf) | 0  1/d  -e/(df) | 0 0 1/f]
//
// DRAM-bound streaming op (604 MB). R3: persistent CTAs + 3-stage cp.async
// pipeline. Loads for tile k are issued at iteration k-2 (LDGSTS -> smem,
// no register roundtrip) and waited with cp.async.wait_group 1, hiding the
// full DRAM latency behind ~2 iterations of compute+store. Ring of 3 x 9KB
// buffers = 27.6KB/CTA; 8 CTAs/SM = 221KB smem, 64 warps resident.
//
// Coalescing: LDGSTS.128 / STG.128, tile-contiguous. Smem banks: staging =
// consecutive float4 (conflict-free); compute addresses word 9*t+k,
// gcd(9,32)=1 -> conflict-free.
//
// Buffer-reuse safety: prefetch at iter k targets the buffer consumed at
// iter k-1; the __syncthreads at the top of iter k orders all threads'
// stage-out LDS of that buffer (STG's data dependency forces LDS completion
// before each thread reaches the barrier) before any new async writes land.

#define THREADS 256
#define ROWS_PER_TILE 256
#define VECS_PER_TILE 576          // 256*9/4 float4 per tile
#define STAGES 3

__device__ __forceinline__ void issue_tile_load(
    float4 (*s)[VECS_PER_TILE], int stage,
    const float4* __restrict__ in, long long tile, long long ntiles, int t)
{
    if (tile < ntiles) {
        const float4* src = in + tile * VECS_PER_TILE;
#pragma unroll
        for (int i = 0; i < 3; i++) {
            int li = t + i * THREADS;
            if (li < VECS_PER_TILE) {
                uint32_t saddr = (uint32_t)__cvta_generic_to_shared(&s[stage][li]);
                asm volatile("cp.async.cg.shared.global [%0], [%1], 16;"
                             :: "r"(saddr), "l"(src + li) : "memory");
            }
        }
    }
    asm volatile("cp.async.commit_group;" ::: "memory");
}

__global__ __launch_bounds__(THREADS, 8) void inv3_pipe_kernel(
    const float4* __restrict__ in, float4* __restrict__ out, long long ntiles)
{
    __shared__ float4 s[STAGES][VECS_PER_TILE];   // 27648 B

    const int t = threadIdx.x;
    const long long stride = gridDim.x;
    const long long tile0 = blockIdx.x;

    // Prologue: two tiles in flight.
    issue_tile_load(s, 0, in, tile0, ntiles, t);
    issue_tile_load(s, 1, in, tile0 + stride, ntiles, t);

    int stage = 0;
    for (long long tile = tile0; tile < ntiles; tile += stride) {
        // Wait for tile's loads (2 groups pending -> leave 1 = the next tile's).
        asm volatile("cp.async.wait_group 1;" ::: "memory");
        __syncthreads();

        // Prefetch tile+2*stride into the buffer consumed last iteration.
        int pre_stage = stage + 2;
        if (pre_stage >= STAGES) pre_stage -= STAGES;
        issue_tile_load(s, pre_stage, in, tile + 2 * stride, ntiles, t);

        // Compute: one row per thread, in place in smem.
        {
            float* p = reinterpret_cast<float*>(&s[stage][0]) + t * 9;
            float a = p[0], b = p[1], c = p[2];
            float d = p[4], e = p[5];
            float f = p[8];

            float ia  = __frcp_rn(a);
            float id  = __frcp_rn(d);
            float iff = __frcp_rn(f);

            float iad = ia * id;
            float o01 = -b * iad;
            float o12 = -e * (id * iff);
            float o02 = (b * e - c * d) * (iad * iff);

            p[0] = ia;
            p[1] = o01;
            p[2] = o02;
            p[3] = 0.0f;
            p[4] = id;
            p[5] = o12;
            p[6] = 0.0f;
            p[7] = 0.0f;
            p[8] = iff;
        }
        __syncthreads();

        // Stage out: coalesced float4 stores.
        {
            const float4* sv = &s[stage][0];
            float4* dst = out + tile * VECS_PER_TILE;
#pragma unroll
            for (int i = 0; i < 3; i++) {
                int li = t + i * THREADS;
                if (li < VECS_PER_TILE)
                    dst[li] = sv[li];
            }
        }

        stage = stage + 1;
        if (stage >= STAGES) stage -= STAGES;
    }
}

// Scalar tail for rows not covered by full tiles (not hit for N=8388608).
__global__ void inv3_tail_kernel(const float* __restrict__ in,
                                 float* __restrict__ out, int nrows)
{
    int row = blockIdx.x * blockDim.x + threadIdx.x;
    if (row >= nrows) return;
    const float* p = in + (long long)row * 9;
    float* q = out + (long long)row * 9;

    float a = p[0], b = p[1], c = p[2];
    float d = p[4], e = p[5];
    float f = p[8];

    float ia  = __frcp_rn(a);
    float id  = __frcp_rn(d);
    float iff = __frcp_rn(f);

    float iad = ia * id;
    q[0] = ia;
    q[1] = -b * iad;
    q[2] = (b * e - c * d) * (iad * iff);
    q[3] = 0.0f;
    q[4] = id;
    q[5] = -e * (id * iff);
    q[6] = 0.0f;
    q[7] = 0.0f;
    q[8] = iff;
}

extern "C" void kernel_launch(void* const* d_in, const int* in_sizes, int n_in,
                              void* d_out, int out_size)
{
    const float* x = (const float*)d_in[0];
    float* y = (float*)d_out;
    long long total_floats = in_sizes[0];
    long long nrows = total_floats / 9;

    long long ntiles = nrows / ROWS_PER_TILE;
    if (ntiles > 0) {
        // Persistent grid: 8 CTAs per SM (152 SMs on GB300).
        long long grid = 152LL * 8;
        if (grid > ntiles) grid = ntiles;
        inv3_pipe_kernel<<<(unsigned)grid, THREADS>>>(
            (const float4*)x, (float4*)y, ntiles);
    }
    long long done = ntiles * ROWS_PER_TILE;
    int rem = (int)(nrows - done);
    if (rem > 0) {
        inv3_tail_kernel<<<(rem + 255) / 256, 256>>>(
            x + done * 9, y + done * 9, rem);
    }
}

// round 4
// speedup vs baseline: 1.1566x; 1.1566x over previous
#include <cuda_runtime.h>
#include <cuda_bf16.h>
#include <cstdint>

// Batched inverse of 3x3 upper-triangular matrices, rows of 9 fp32.
//   in : [a b c | . d e | . . f]
//   out: [1/a  -b/(ad)  (be-cd)/(adf) | 0  1/d  -e/(df) | 0 0 1/f]
//
// DRAM-bound streaming op (604 MB, zero reuse). R4 = R2 (best: 85.2us kernel,
// 92% occ, DRAM 81.3%) + streaming cache hints: __ldcs / __stcs mark both
// streams evict-first so the 604MB one-touch stream doesn't churn L2 and
// dirty lines write back eagerly.
//
// Shape (unchanged from R2): 256 rows / 256 threads / 9KB smem -> 8 CTAs/SM,
// 64 warps. All global traffic LDG.128/STG.128 block-contiguous. Smem banks:
// staging = consecutive float4 (conflict-free); compute addresses word 9t+k,
// gcd(9,32)=1 -> conflict-free.

#define THREADS 256
#define ROWS_PER_BLOCK 256
#define FLOATS_PER_BLOCK (ROWS_PER_BLOCK * 9)   // 2304
#define VEC_PER_BLOCK (FLOATS_PER_BLOCK / 4)    // 576

__global__ __launch_bounds__(THREADS, 8) void inv3_vec_kernel(
    const float4* __restrict__ in, float4* __restrict__ out)
{
    __shared__ float s[FLOATS_PER_BLOCK];  // 9216 B

    const long long base_vec = (long long)blockIdx.x * VEC_PER_BLOCK;
    float4* sv = reinterpret_cast<float4*>(s);

    // ---- Stage in: 576 float4, 2-3 per thread, coalesced, evict-first ----
#pragma unroll
    for (int i = 0; i < 3; i++) {
        int li = threadIdx.x + i * THREADS;
        if (li < VEC_PER_BLOCK)
            sv[li] = __ldcs(&in[base_vec + li]);
    }
    __syncthreads();

    // ---- Compute: 1 row per thread, in place in smem ----
    {
        float* p = &s[threadIdx.x * 9];
        float a = p[0], b = p[1], c = p[2];
        float d = p[4], e = p[5];
        float f = p[8];

        float ia  = __frcp_rn(a);
        float id  = __frcp_rn(d);
        float iff = __frcp_rn(f);

        float iad = ia * id;
        float o01 = -b * iad;
        float o12 = -e * (id * iff);
        float o02 = (b * e - c * d) * (iad * iff);

        p[0] = ia;
        p[1] = o01;
        p[2] = o02;
        p[3] = 0.0f;
        p[4] = id;
        p[5] = o12;
        p[6] = 0.0f;
        p[7] = 0.0f;
        p[8] = iff;
    }
    __syncthreads();

    // ---- Stage out: 576 float4, coalesced, streaming stores ----
#pragma unroll
    for (int i = 0; i < 3; i++) {
        int li = threadIdx.x + i * THREADS;
        if (li < VEC_PER_BLOCK)
            __stcs(&out[base_vec + li], sv[li]);
    }
}

// Scalar tail for rows not covered by full blocks (not hit for N=8388608).
__global__ void inv3_tail_kernel(const float* __restrict__ in,
                                 float* __restrict__ out, int nrows)
{
    int row = blockIdx.x * blockDim.x + threadIdx.x;
    if (row >= nrows) return;
    const float* p = in + (long long)row * 9;
    float* q = out + (long long)row * 9;

    float a = p[0], b = p[1], c = p[2];
    float d = p[4], e = p[5];
    float f = p[8];

    float ia  = __frcp_rn(a);
    float id  = __frcp_rn(d);
    float iff = __frcp_rn(f);

    float iad = ia * id;
    q[0] = ia;
    q[1] = -b * iad;
    q[2] = (b * e - c * d) * (iad * iff);
    q[3] = 0.0f;
    q[4] = id;
    q[5] = -e * (id * iff);
    q[6] = 0.0f;
    q[7] = 0.0f;
    q[8] = iff;
}

extern "C" void kernel_launch(void* const* d_in, const int* in_sizes, int n_in,
                              void* d_out, int out_size)
{
    const float* x = (const float*)d_in[0];
    float* y = (float*)d_out;
    long long total_floats = in_sizes[0];
    long long nrows = total_floats / 9;

    long long nblocks = nrows / ROWS_PER_BLOCK;
    if (nblocks > 0) {
        inv3_vec_kernel<<<(unsigned)nblocks, THREADS>>>(
            (const float4*)x, (float4*)y);
    }
    long long done = nblocks * ROWS_PER_BLOCK;
    int rem = (int)(nrows - done);
    if (rem > 0) {
        inv3_tail_kernel<<<(rem + 255) / 256, 256>>>(
            x + done * 9, y + done * 9, rem);
    }
}

// round 5
// speedup vs baseline: 1.1682x; 1.0100x over previous
#include <cuda_runtime.h>
#include <cuda_bf16.h>
#include <cstdint>

// Batched inverse of 3x3 upper-triangular matrices, rows of 9 fp32.
//   in : [a b c | . d e | . . f]
//   out: [1/a  -b/(ad)  (be-cd)/(adf) | 0  1/d  -e/(df) | 0 0 1/f]
//
// R5 insight: 3x MUFU.RCP per row x 8.39M rows = 25.2M MUFU ops ~= 87us at
// ~1 rcp/cyc/SM -- the kernel was MUFU-bound, masquerading as a DRAM ceiling
// (DRAM pinned at 81% across 3 structurally different kernels). Replace the
// three reciprocals with ONE: ip = rcp(a*d*f), then
//   1/a=(d*f)*ip  1/d=(a*f)*ip  1/f=(a*d)*ip
//   o01=-(b*f)*ip o12=-(e*a)*ip o02=(b*e-c*d)*ip
// 1 MUFU + ~13 FMA ops/row; FMA pipe was at 6.3%, tons of headroom.
// Diagonal in [0.5,1.5) so a*d*f in [0.125,3.4): no overflow/underflow.
//
// Shape = R2/R4 best: 256 rows / 256 threads / 9KB smem -> 8 CTAs/SM,
// 64 warps; LDG.128/STG.128 coalesced with evict-first hints; smem compute
// addresses word 9t+k, gcd(9,32)=1 -> conflict-free.

#define THREADS 256
#define ROWS_PER_BLOCK 256
#define FLOATS_PER_BLOCK (ROWS_PER_BLOCK * 9)   // 2304
#define VEC_PER_BLOCK (FLOATS_PER_BLOCK / 4)    // 576

__device__ __forceinline__ void inv3_row(const float* __restrict__ p,
                                         float* __restrict__ q)
{
    float a = p[0], b = p[1], c = p[2];
    float d = p[4], e = p[5];
    float f = p[8];

    float ad = a * d;
    float df = d * f;
    float af = a * f;
    float ip = __frcp_rn(ad * f);      // single reciprocal: 1/(a d f)

    float ia  = df * ip;               // 1/a
    float id  = af * ip;               // 1/d
    float iff = ad * ip;               // 1/f
    float o01 = -(b * f) * ip;         // -b/(ad)
    float o12 = -(e * a) * ip;         // -e/(df)
    float o02 = (b * e - c * d) * ip;  // (be - cd)/(adf)

    q[0] = ia;
    q[1] = o01;
    q[2] = o02;
    q[3] = 0.0f;
    q[4] = id;
    q[5] = o12;
    q[6] = 0.0f;
    q[7] = 0.0f;
    q[8] = iff;
}

__global__ __launch_bounds__(THREADS, 8) void inv3_vec_kernel(
    const float4* __restrict__ in, float4* __restrict__ out)
{
    __shared__ float s[FLOATS_PER_BLOCK];  // 9216 B

    const long long base_vec = (long long)blockIdx.x * VEC_PER_BLOCK;
    float4* sv = reinterpret_cast<float4*>(s);

    // ---- Stage in: 576 float4, coalesced, evict-first ----
#pragma unroll
    for (int i = 0; i < 3; i++) {
        int li = threadIdx.x + i * THREADS;
        if (li < VEC_PER_BLOCK)
            sv[li] = __ldcs(&in[base_vec + li]);
    }
    __syncthreads();

    // ---- Compute: 1 row per thread, in place in smem ----
    {
        float* p = &s[threadIdx.x * 9];
        inv3_row(p, p);
    }
    __syncthreads();

    // ---- Stage out: 576 float4, coalesced, streaming stores ----
#pragma unroll
    for (int i = 0; i < 3; i++) {
        int li = threadIdx.x + i * THREADS;
        if (li < VEC_PER_BLOCK)
            __stcs(&out[base_vec + li], sv[li]);
    }
}

// Scalar tail for rows not covered by full blocks (not hit for N=8388608).
__global__ void inv3_tail_kernel(const float* __restrict__ in,
                                 float* __restrict__ out, int nrows)
{
    int row = blockIdx.x * blockDim.x + threadIdx.x;
    if (row >= nrows) return;
    inv3_row(in + (long long)row * 9, out + (long long)row * 9);
}

extern "C" void kernel_launch(void* const* d_in, const int* in_sizes, int n_in,
                              void* d_out, int out_size)
{
    const float* x = (const float*)d_in[0];
    float* y = (float*)d_out;
    long long total_floats = in_sizes[0];
    long long nrows = total_floats / 9;

    long long nblocks = nrows / ROWS_PER_BLOCK;
    if (nblocks > 0) {
        inv3_vec_kernel<<<(unsigned)nblocks, THREADS>>>(
            (const float4*)x, (float4*)y);
    }
    long long done = nblocks * ROWS_PER_BLOCK;
    int rem = (int)(nrows - done);
    if (rem > 0) {
        inv3_tail_kernel<<<(rem + 255) / 256, 256>>>(
            x + done * 9, y + done * 9, rem);
    }
}